// round 14
// baseline (speedup 1.0000x reference)
#include <cuda_runtime.h>
#include <math.h>
#include <stdint.h>

#define Bn 4
#define Cc 192
#define Dd 4
#define Hh 16
#define Ww 16
#define LL 1024
#define DIN 384
#define DSTATE 64
#define DTRANK 12
#define DCONV 4
#define MM (Bn * LL)          // 4096
#define HIDN (Bn * LL * 48)   // 196608

// ---------------- scratch ----------------
__device__ float g_pooled[Bn * Cc];
__device__ float g_hidp[27 * HIDN];
__device__ float g_hidT[HIDN];          // [bl][48]
__device__ float g_offs[Bn * LL * 3];
__device__ float g_xs[MM * Cc];
__device__ float g_xz[MM * 2 * DIN];
__device__ float g_xi[MM * DIN];
__device__ float g_dbl[MM * 140];
__device__ float g_y[MM * DIN];
__device__ float g_p2p[Bn * 16 * Cc];
__device__ float g_xT[MM * Cc];         // [bl][c]
// pre-transposed weights [K][N]
__device__ float g_tin[Cc * 768];
__device__ float g_tcat[Cc * Cc];
__device__ float g_bcat[Cc];
__device__ float g_tx[DIN * 192];       // x_proj padded 140->192
__device__ float g_tout[DIN * Cc];
__device__ float g_tw1[27 * Cc * 48];   // conv1 [tap][c][o] unpadded

__device__ __forceinline__ float sigmoidf_(float x) { return 1.f / (1.f + expf(-x)); }
__device__ __forceinline__ float geluf_(float x) {
    return 0.5f * x * (1.f + erff(x * 0.70710678118654752440f));
}
__device__ __forceinline__ float softplusf_(float x) {
    return (x > 20.f) ? x : log1pf(expf(x));
}

// ---------------- merged prep (weight transposes) + x transpose + pooled mean ----------------
#define PREP_TOTAL (147456 + 36864 + 192 + 73728 + 73728 + 248832)
#define PREP_BLKS ((PREP_TOTAL + 255) / 256)
__global__ void prepxt_kernel(const float* __restrict__ x,
                              const float* __restrict__ in_proj_w,
                              const float* __restrict__ px_w, const float* __restrict__ py_w,
                              const float* __restrict__ pz_w,
                              const float* __restrict__ px_b, const float* __restrict__ py_b,
                              const float* __restrict__ pz_b,
                              const float* __restrict__ x_proj_w,
                              const float* __restrict__ out_proj_w,
                              const float* __restrict__ off_w1) {
    int bx = blockIdx.x;
    if (bx < 768) {
        __shared__ float tile[32][33];
        int l0 = (bx & 31) * 32;
        int c0 = ((bx >> 5) % 6) * 32;
        int b = bx / 192;
        int tx = threadIdx.x & 31, ty = threadIdx.x >> 5;
        #pragma unroll
        for (int i = 0; i < 32; i += 8)
            tile[ty + i][tx] = x[(b * Cc + c0 + ty + i) * LL + l0 + tx];
        __syncthreads();
        #pragma unroll
        for (int i = 0; i < 32; i += 8)
            g_xT[(b * LL + l0 + ty + i) * Cc + c0 + tx] = tile[tx][ty + i];
        return;
    }
    if (bx < 1536) {
        __shared__ float sm[256];
        int bc = bx - 768;
        const float* p = x + bc * LL;
        float s = 0.f;
        for (int i = threadIdx.x; i < LL; i += 256) s += p[i];
        sm[threadIdx.x] = s; __syncthreads();
        for (int st = 128; st > 0; st >>= 1) {
            if (threadIdx.x < st) sm[threadIdx.x] += sm[threadIdx.x + st];
            __syncthreads();
        }
        if (threadIdx.x == 0) g_pooled[bc] = sm[0] * (1.f / (float)LL);
        return;
    }
    int t = (bx - 1536) * 256 + threadIdx.x;
    if (t < 147456) { int k = t / 768, n = t % 768; g_tin[t] = in_proj_w[n * Cc + k]; return; }
    t -= 147456;
    if (t < 36864) {
        int k = t / Cc, n = t % Cc; int br = n >> 6, oo = n & 63;
        const float* s = (br == 0) ? px_w : (br == 1) ? py_w : pz_w;
        g_tcat[t] = s[oo * Cc + k]; return;
    }
    t -= 36864;
    if (t < Cc) {
        const float* s = (t < 64) ? px_b : (t < 128) ? py_b : pz_b;
        g_bcat[t] = s[t & 63]; return;
    }
    t -= Cc;
    if (t < 73728) { int k = t / 192, n = t % 192;
        g_tx[t] = (n < 140) ? x_proj_w[n * DIN + k] : 0.f; return; }
    t -= 73728;
    if (t < 73728) { int k = t / Cc, n = t % Cc; g_tout[t] = out_proj_w[n * DIN + k]; return; }
    t -= 73728;
    if (t < 248832) {
        int tap = t / (Cc * 48); int rem = t % (Cc * 48); int c = rem / 48, o = rem % 48;
        g_tw1[t] = off_w1[(o * Cc + c) * 27 + tap]; return;
    }
}

// ---------------- conv1 implicit GEMM, unpadded N=48: grid (64 m-tiles, 27 taps) ----------------
__global__ void conv1_kernel() {
    __shared__ float sA[64][66];
    __shared__ float sW[64][56];
    int m0 = blockIdx.x * 64;
    int tap = blockIdx.y;
    int kd = tap / 9, kh = (tap / 3) % 3, kw = tap % 3;
    int loff = (kd - 1) * 256 + (kh - 1) * 16 + (kw - 1);
    int tid = threadIdx.x;
    int tn = tid & 7, tm = tid >> 3;
    float acc[4][6] = {};
    for (int k0 = 0; k0 < Cc; k0 += 64) {
        #pragma unroll
        for (int t = 0; t < 16; ++t) {
            int idx = tid + t * 128;
            int r = idx >> 5, c2 = idx & 31;
            int ll = (m0 & 1023) + r;
            int z = ll >> 8, y = (ll >> 4) & 15, xx = ll & 15;
            bool ok = ((unsigned)(z + kd - 1) < 4u) && ((unsigned)(y + kh - 1) < 16u)
                   && ((unsigned)(xx + kw - 1) < 16u);
            float2 v = make_float2(0.f, 0.f);
            if (ok) v = *(const float2*)&g_xT[(m0 + r + loff) * Cc + k0 + c2 * 2];
            *(float2*)&sA[r][c2 * 2] = v;
        }
        #pragma unroll
        for (int t = 0; t < 6; ++t) {
            int idx = tid + t * 128;
            int r = idx / 12, c4 = idx % 12;
            *(float4*)&sW[r][c4 * 4] = *(const float4*)&g_tw1[(tap * Cc + k0 + r) * 48 + c4 * 4];
        }
        __syncthreads();
        #pragma unroll
        for (int k = 0; k < 64; ++k) {
            float a0 = sA[tm * 4 + 0][k], a1 = sA[tm * 4 + 1][k];
            float a2 = sA[tm * 4 + 2][k], a3 = sA[tm * 4 + 3][k];
            float4 wlo = *(const float4*)&sW[k][tn * 4];
            float2 whi = *(const float2*)&sW[k][32 + tn * 2];
            acc[0][0] += a0*wlo.x; acc[0][1] += a0*wlo.y; acc[0][2] += a0*wlo.z;
            acc[0][3] += a0*wlo.w; acc[0][4] += a0*whi.x; acc[0][5] += a0*whi.y;
            acc[1][0] += a1*wlo.x; acc[1][1] += a1*wlo.y; acc[1][2] += a1*wlo.z;
            acc[1][3] += a1*wlo.w; acc[1][4] += a1*whi.x; acc[1][5] += a1*whi.y;
            acc[2][0] += a2*wlo.x; acc[2][1] += a2*wlo.y; acc[2][2] += a2*wlo.z;
            acc[2][3] += a2*wlo.w; acc[2][4] += a2*whi.x; acc[2][5] += a2*whi.y;
            acc[3][0] += a3*wlo.x; acc[3][1] += a3*wlo.y; acc[3][2] += a3*wlo.z;
            acc[3][3] += a3*wlo.w; acc[3][4] += a3*whi.x; acc[3][5] += a3*whi.y;
        }
        __syncthreads();
    }
    float* dst = g_hidp + tap * HIDN;
    #pragma unroll
    for (int i = 0; i < 4; ++i) {
        int l = m0 + tm * 4 + i;
        *(float4*)&dst[l * 48 + tn * 4] =
            make_float4(acc[i][0], acc[i][1], acc[i][2], acc[i][3]);
        *(float2*)&dst[l * 48 + 32 + tn * 2] = make_float2(acc[i][4], acc[i][5]);
    }
}

// ---------------- reduce 27 partials + bias + gelu (float4) ----------------
__global__ void hidred_kernel(const float* __restrict__ b1) {
    int t = blockIdx.x * 256 + threadIdx.x;
    if (t >= HIDN / 4) return;
    int o4 = t % 12;
    float4 s = *(const float4*)&b1[o4 * 4];
    #pragma unroll
    for (int k = 0; k < 27; ++k) {
        float4 v = *(const float4*)&g_hidp[k * HIDN + t * 4];
        s.x += v.x; s.y += v.y; s.z += v.z; s.w += v.w;
    }
    float4 r = make_float4(geluf_(s.x), geluf_(s.y), geluf_(s.z), geluf_(s.w));
    *(float4*)&g_hidT[t * 4] = r;
}

// ---------------- conv2: one warp per voxel ----------------
__global__ void conv2_kernel(const float* __restrict__ w2, const float* __restrict__ b2) {
    __shared__ float ws[3 * 48 * 27];
    int tid = threadIdx.x;
    for (int i = tid; i < 3 * 48 * 27; i += 128) ws[i] = w2[i];
    __syncthreads();
    int lane = tid & 31, warpid = tid >> 5;
    int bl = blockIdx.x * 4 + warpid;
    int ll = bl & 1023;
    int z = ll >> 8, y = (ll >> 4) & 15, xx = ll & 15;
    int c2 = 32 + (lane & 15);
    float m2 = (lane < 16) ? 1.f : 0.f;
    float s0 = 0.f, s1 = 0.f, s2 = 0.f;
    #pragma unroll
    for (int tap = 0; tap < 27; ++tap) {
        int kd = tap / 9, kh = (tap / 3) % 3, kw = tap % 3;
        bool ok = ((unsigned)(z + kd - 1) < 4u) && ((unsigned)(y + kh - 1) < 16u)
               && ((unsigned)(xx + kw - 1) < 16u);
        if (ok) {
            int bl2 = bl + (kd - 1) * 256 + (kh - 1) * 16 + (kw - 1);
            float h0 = g_hidT[bl2 * 48 + lane];
            float h1 = m2 * g_hidT[bl2 * 48 + c2 - ((lane < 16) ? 0 : 16)];
            s0 += h0 * ws[(0 * 48 + lane) * 27 + tap] + h1 * ws[(0 * 48 + c2) * 27 + tap];
            s1 += h0 * ws[(1 * 48 + lane) * 27 + tap] + h1 * ws[(1 * 48 + c2) * 27 + tap];
            s2 += h0 * ws[(2 * 48 + lane) * 27 + tap] + h1 * ws[(2 * 48 + c2) * 27 + tap];
        }
    }
    #pragma unroll
    for (int off = 16; off; off >>= 1) {
        s0 += __shfl_xor_sync(0xffffffffu, s0, off);
        s1 += __shfl_xor_sync(0xffffffffu, s1, off);
        s2 += __shfl_xor_sync(0xffffffffu, s2, off);
    }
    if (lane == 0) {
        g_offs[bl * 3 + 0] = s0 + b2[0];
        g_offs[bl * 3 + 1] = s1 + b2[1];
        g_offs[bl * 3 + 2] = s2 + b2[2];
    }
}

// ---------------- conflict-free tiled GEMM ----------------
// EPI 0: plain (guard NR)
// EPI 1: g_xs = (acc+bias)*softmax-gate + posemb-gather
// EPI 2: transposed out + per-tile partial channel means into g_p2p
// FUSEDW: A-fill computes depthwise-conv+silu from g_xz (K must be DIN); by==0 also stores g_xi
template<int K, int NP, int NR, int EPI, bool FUSEDW>
__global__ void gemm64(const float* __restrict__ A, const float* __restrict__ Wt,
                       float* __restrict__ outp,
                       const float* __restrict__ wg_w, const float* __restrict__ wg_b) {
    __shared__ float sA[64][66];
    __shared__ float sW[64][72];
    __shared__ float slg[3];
    int m0 = blockIdx.x * 64;
    int n0 = blockIdx.y * 64;
    int tid = threadIdx.x;
    int tn = tid & 7, tm = tid >> 3;
    if (EPI == 1) {
        int warpid = tid >> 5, lane = tid & 31;
        if (warpid < 3) {
            int b = m0 >> 10;
            float s = 0.f;
            for (int c = lane; c < Cc; c += 32) s += g_pooled[b * Cc + c] * wg_w[warpid * Cc + c];
            #pragma unroll
            for (int off = 16; off; off >>= 1) s += __shfl_xor_sync(0xffffffffu, s, off);
            if (lane == 0) slg[warpid] = s + wg_b[warpid];
        }
    }
    float acc[4][8] = {};
    for (int k0 = 0; k0 < K; k0 += 64) {
        if (FUSEDW) {
            // fused depthwise causal conv + silu from g_xz; wg_w=conv_w, wg_b=conv_b
            #pragma unroll
            for (int t = 0; t < 32; ++t) {
                int idx = tid + t * 128;
                int r = idx >> 6, dc = idx & 63;
                int d = k0 + dc;
                int bl = m0 + r;
                int l = bl & 1023;
                const float* base = g_xz + (bl - l) * (2 * DIN) + d;
                float s = wg_b[d];
                #pragma unroll
                for (int k = 0; k < DCONV; ++k) {
                    int ll = l - (DCONV - 1) + k;
                    if (ll >= 0) s += base[ll * (2 * DIN)] * wg_w[d * DCONV + k];
                }
                float v = s * sigmoidf_(s);
                sA[r][dc] = v;
                if (blockIdx.y == 0) g_xi[bl * DIN + d] = v;
            }
        } else {
            #pragma unroll
            for (int t = 0; t < 16; ++t) {
                int idx = tid + t * 128;
                int r = idx >> 5, c2 = idx & 31;
                *(float2*)&sA[r][c2 * 2] = *(const float2*)&A[(m0 + r) * K + k0 + c2 * 2];
            }
        }
        #pragma unroll
        for (int t = 0; t < 8; ++t) {
            int idx = tid + t * 128;
            int r = idx >> 4, c4 = idx & 15;
            *(float4*)&sW[r][c4 * 4] = *(const float4*)&Wt[(k0 + r) * NP + n0 + c4 * 4];
        }
        __syncthreads();
        #pragma unroll
        for (int k = 0; k < 64; ++k) {
            float a0 = sA[tm * 4 + 0][k], a1 = sA[tm * 4 + 1][k];
            float a2 = sA[tm * 4 + 2][k], a3 = sA[tm * 4 + 3][k];
            float4 wlo = *(const float4*)&sW[k][tn * 4];
            float4 whi = *(const float4*)&sW[k][32 + tn * 4];
            acc[0][0] += a0*wlo.x; acc[0][1] += a0*wlo.y; acc[0][2] += a0*wlo.z; acc[0][3] += a0*wlo.w;
            acc[0][4] += a0*whi.x; acc[0][5] += a0*whi.y; acc[0][6] += a0*whi.z; acc[0][7] += a0*whi.w;
            acc[1][0] += a1*wlo.x; acc[1][1] += a1*wlo.y; acc[1][2] += a1*wlo.z; acc[1][3] += a1*wlo.w;
            acc[1][4] += a1*whi.x; acc[1][5] += a1*whi.y; acc[1][6] += a1*whi.z; acc[1][7] += a1*whi.w;
            acc[2][0] += a2*wlo.x; acc[2][1] += a2*wlo.y; acc[2][2] += a2*wlo.z; acc[2][3] += a2*wlo.w;
            acc[2][4] += a2*whi.x; acc[2][5] += a2*whi.y; acc[2][6] += a2*whi.z; acc[2][7] += a2*whi.w;
            acc[3][0] += a3*wlo.x; acc[3][1] += a3*wlo.y; acc[3][2] += a3*wlo.z; acc[3][3] += a3*wlo.w;
            acc[3][4] += a3*whi.x; acc[3][5] += a3*whi.y; acc[3][6] += a3*whi.z; acc[3][7] += a3*whi.w;
        }
        __syncthreads();
    }
    if (EPI == 0) {
        #pragma unroll
        for (int i = 0; i < 4; ++i) {
            int l = m0 + tm * 4 + i;
            if (NP == NR) {
                *(float4*)&outp[l * NR + n0 + tn * 4] =
                    make_float4(acc[i][0], acc[i][1], acc[i][2], acc[i][3]);
                *(float4*)&outp[l * NR + n0 + 32 + tn * 4] =
                    make_float4(acc[i][4], acc[i][5], acc[i][6], acc[i][7]);
            } else {
                #pragma unroll
                for (int j = 0; j < 4; ++j) {
                    int n = n0 + tn * 4 + j;
                    if (n < NR) outp[l * NR + n] = acc[i][j];
                    int n2 = n0 + 32 + tn * 4 + j;
                    if (n2 < NR) outp[l * NR + n2] = acc[i][j + 4];
                }
            }
        }
    } else if (EPI == 1) {
        float mx = fmaxf(slg[0], fmaxf(slg[1], slg[2]));
        float e0 = expf(slg[0] - mx), e1 = expf(slg[1] - mx), e2 = expf(slg[2] - mx);
        int br = n0 >> 6;
        float wt = ((br == 0) ? e0 : (br == 1) ? e1 : e2) / (e0 + e1 + e2);
        int b = m0 >> 10;
        #pragma unroll
        for (int i = 0; i < 4; ++i) {
            int l = m0 + tm * 4 + i;
            float gx = g_offs[l * 3 + 0];
            float gy = g_offs[l * 3 + 1];
            float gz = g_offs[l * 3 + 2];
            float ixf = ((gx + 1.f) * (float)Ww - 1.f) * 0.5f;
            float iyf = ((gy + 1.f) * (float)Hh - 1.f) * 0.5f;
            float izf = ((gz + 1.f) * (float)Dd - 1.f) * 0.5f;
            float x0f = floorf(ixf), y0f = floorf(iyf), z0f = floorf(izf);
            int idxs[8]; float w8[8];
            int corner = 0;
            #pragma unroll
            for (int dz = 0; dz < 2; ++dz)
            #pragma unroll
            for (int dy = 0; dy < 2; ++dy)
            #pragma unroll
            for (int dx = 0; dx < 2; ++dx) {
                float xc = x0f + dx, yc = y0f + dy, zc = z0f + dz;
                float wg = (1.f - fabsf(ixf - xc)) * (1.f - fabsf(iyf - yc))
                         * (1.f - fabsf(izf - zc));
                bool valid = (xc >= 0.f) && (xc < (float)Ww) && (yc >= 0.f)
                          && (yc < (float)Hh) && (zc >= 0.f) && (zc < (float)Dd);
                int xi_ = (int)fminf(fmaxf(xc, 0.f), (float)(Ww - 1));
                int yi_ = (int)fminf(fmaxf(yc, 0.f), (float)(Hh - 1));
                int zi_ = (int)fminf(fmaxf(zc, 0.f), (float)(Dd - 1));
                idxs[corner] = b * LL + (zi_ * Hh + yi_) * Ww + xi_;
                w8[corner] = wg * (valid ? 1.f : 0.f);
                ++corner;
            }
            #pragma unroll
            for (int j = 0; j < 4; ++j) {
                int c1 = n0 + tn * 4 + j;
                int c2 = n0 + 32 + tn * 4 + j;
                float pe1 = 0.f, pe2 = 0.f;
                #pragma unroll
                for (int k = 0; k < 8; ++k) {
                    pe1 += g_xT[idxs[k] * Cc + c1] * w8[k];
                    pe2 += g_xT[idxs[k] * Cc + c2] * w8[k];
                }
                outp[l * Cc + c1] = (acc[i][j] + g_bcat[c1]) * wt + pe1;
                outp[l * Cc + c2] = (acc[i][j + 4] + g_bcat[c2]) * wt + pe2;
            }
        }
    } else {
        float* sT = &sW[0][0];
        #pragma unroll
        for (int i = 0; i < 4; ++i) {
            int ml = tm * 4 + i;
            #pragma unroll
            for (int j = 0; j < 4; ++j) {
                sT[(tn * 4 + j) * 68 + ml] = acc[i][j];
                sT[(32 + tn * 4 + j) * 68 + ml] = acc[i][j + 4];
            }
        }
        __syncthreads();
        int b = m0 >> 10, l0 = m0 & 1023;
        #pragma unroll
        for (int t = 0; t < 8; ++t) {
            int idx = tid + t * 128;
            int nr = idx >> 4, c4 = idx & 15;
            float4 v = *(const float4*)&sT[nr * 68 + c4 * 4];
            *(float4*)&outp[((b * Cc + n0 + nr) << 10) + l0 + c4 * 4] = v;
        }
        if (tid < 64) {
            float s = 0.f;
            #pragma unroll 8
            for (int ll = 0; ll < 64; ++ll) s += sT[tid * 68 + ll];
            int ltile = (m0 & 1023) >> 6;
            g_p2p[(b * 16 + ltile) * Cc + n0 + tid] = s;
        }
    }
}

// ---------------- selective scan with fused delta (smem prologue, no inner-loop shfl) ----------------
__global__ void scan_kernel(const float* __restrict__ a_log, const float* __restrict__ Dskip,
                            const float* __restrict__ dtw, const float* __restrict__ dtb) {
    __shared__ float sm[8][32][33];
    __shared__ float sDT[8][32];
    __shared__ float sU[8][32];
    int wIn = threadIdx.x >> 5, lane = threadIdx.x & 31;
    int bd = blockIdx.x * 8 + wIn;
    int b = bd / DIN, d = bd % DIN;
    float (*S)[33] = sm[wIn];
    float a0 = -expf(a_log[d * DSTATE + lane]);
    float a1 = -expf(a_log[d * DSTATE + 32 + lane]);
    float dsk = Dskip[d];
    float wdt[DTRANK];
    #pragma unroll
    for (int r = 0; r < DTRANK; ++r) wdt[r] = dtw[d * DTRANK + r];
    float dtb_d = dtb[d];
    float h0 = 0.f, h1 = 0.f;
    const float* uptr = g_xi + b * LL * DIN + d;
    const float* dblb = g_dbl + b * LL * 140;
    const float* zbase = g_xz + b * LL * (2 * DIN) + DIN + d;
    float* yo = g_y + b * LL * DIN + d;
    for (int l0 = 0; l0 < LL; l0 += 32) {
        int lm = l0 + lane;
        {   // prologue: lane's own l -> delta, u
            const float* rowm = dblb + lm * 140;
            float accd = dtb_d;
            #pragma unroll
            for (int r = 0; r < DTRANK; ++r) accd += __ldg(rowm + r) * wdt[r];
            sDT[wIn][lane] = softplusf_(accd);
            sU[wIn][lane] = __ldg(uptr + lm * DIN);
        }
        __syncwarp();
        #pragma unroll 4
        for (int j = 0; j < 32; ++j) {
            int l = l0 + j;
            float dt = sDT[wIn][j];
            float u = sU[wIn][j];
            const float* row = dblb + l * 140;
            float b0 = __ldg(row + 12 + lane), b1v = __ldg(row + 44 + lane);
            float c0 = __ldg(row + 76 + lane), c1 = __ldg(row + 108 + lane);
            float du = dt * u;
            h0 = __expf(dt * a0) * h0 + du * b0;
            h1 = __expf(dt * a1) * h1 + du * b1v;
            S[j][lane] = h0 * c0 + h1 * c1;
        }
        __syncwarp();
        float s = 0.f;
        #pragma unroll
        for (int k = 0; k < 32; ++k) s += S[lane][k];
        float u2 = sU[wIn][lane];
        float z = __ldg(zbase + lm * (2 * DIN));
        yo[lm * DIN] = (s + u2 * dsk) * (z * sigmoidf_(z));
        __syncwarp();
    }
}

// ---------------- fused channel attention + scale (with partial-mean reduce) ----------------
__global__ void ca_scale_kernel(const float* __restrict__ w1, const float* __restrict__ b1,
                                const float* __restrict__ w2, const float* __restrict__ b2,
                                float* __restrict__ out) {
    int b = blockIdx.x >> 5;
    int chunk = blockIdx.x & 31;
    int tid = threadIdx.x;
    __shared__ float p[Cc];
    __shared__ float hid[48];
    __shared__ float attn[Cc];
    if (tid < Cc) {
        float s = 0.f;
        #pragma unroll
        for (int t = 0; t < 16; ++t) s += g_p2p[(b * 16 + t) * Cc + tid];
        p[tid] = s * (1.f / (float)LL);
    }
    __syncthreads();
    if (tid < 48) {
        const float* wr = w1 + tid * Cc;
        float s = b1[tid];
        #pragma unroll 8
        for (int k = 0; k < Cc; ++k) s += p[k] * wr[k];
        hid[tid] = geluf_(s);
    }
    __syncthreads();
    if (tid < Cc) {
        const float* wr2 = w2 + tid * 48;
        float s = b2[tid];
        #pragma unroll
        for (int j = 0; j < 48; ++j) s += hid[j] * wr2[j];
        attn[tid] = sigmoidf_(s);
    }
    __syncthreads();
    int l0 = chunk * 32;
    for (int e = tid; e < Cc * 32; e += 256) {
        int c = e >> 5, l = l0 + (e & 31);
        out[(b * Cc + c) * LL + l] *= attn[c];
    }
}

extern "C" void kernel_launch(void* const* d_in, const int* in_sizes, int n_in,
                              void* d_out, int out_size) {
    const float* x         = (const float*)d_in[0];
    const float* px_w      = (const float*)d_in[1];
    const float* px_b      = (const float*)d_in[2];
    const float* py_w      = (const float*)d_in[3];
    const float* py_b      = (const float*)d_in[4];
    const float* pz_w      = (const float*)d_in[5];
    const float* pz_b      = (const float*)d_in[6];
    const float* wg_w      = (const float*)d_in[7];
    const float* wg_b      = (const float*)d_in[8];
    const float* off_w1    = (const float*)d_in[9];
    const float* off_b1    = (const float*)d_in[10];
    const float* off_w2    = (const float*)d_in[11];
    const float* off_b2    = (const float*)d_in[12];
    const float* in_proj_w = (const float*)d_in[13];
    const float* conv_w    = (const float*)d_in[14];
    const float* conv_b    = (const float*)d_in[15];
    const float* x_proj_w  = (const float*)d_in[16];
    const float* dt_proj_w = (const float*)d_in[17];
    const float* dt_proj_b = (const float*)d_in[18];
    const float* A_log     = (const float*)d_in[19];
    const float* D_skip    = (const float*)d_in[20];
    const float* out_proj_w = (const float*)d_in[21];
    const float* ca_w1     = (const float*)d_in[22];
    const float* ca_b1     = (const float*)d_in[23];
    const float* ca_w2     = (const float*)d_in[24];
    const float* ca_b2     = (const float*)d_in[25];
    float* out = (float*)d_out;

    float *g_xT_p, *g_xs_p, *g_xz_p, *g_dbl_p, *g_y_p;
    float *g_tin_p, *g_tcat_p, *g_tx_p, *g_tout_p;
    cudaGetSymbolAddress((void**)&g_xT_p, g_xT);
    cudaGetSymbolAddress((void**)&g_xs_p, g_xs);
    cudaGetSymbolAddress((void**)&g_xz_p, g_xz);
    cudaGetSymbolAddress((void**)&g_dbl_p, g_dbl);
    cudaGetSymbolAddress((void**)&g_y_p, g_y);
    cudaGetSymbolAddress((void**)&g_tin_p, g_tin);
    cudaGetSymbolAddress((void**)&g_tcat_p, g_tcat);
    cudaGetSymbolAddress((void**)&g_tx_p, g_tx);
    cudaGetSymbolAddress((void**)&g_tout_p, g_tout);

    prepxt_kernel<<<1536 + PREP_BLKS, 256>>>(x, in_proj_w, px_w, py_w, pz_w,
                                             px_b, py_b, pz_b, x_proj_w, out_proj_w, off_w1);
    conv1_kernel<<<dim3(64, 27), 128>>>();
    hidred_kernel<<<(HIDN / 4 + 255) / 256, 256>>>(off_b1);
    conv2_kernel<<<MM / 4, 128>>>(off_w2, off_b2);
    gemm64<Cc, Cc, Cc, 1, false><<<dim3(64, 3), 128>>>(g_xT_p, g_tcat_p, g_xs_p, wg_w, wg_b);
    gemm64<Cc, 768, 768, 0, false><<<dim3(64, 12), 128>>>(g_xs_p, g_tin_p, g_xz_p, nullptr, nullptr);
    // xproj with fused depthwise conv + silu (A built from g_xz; writes g_xi for scan)
    gemm64<DIN, 192, 140, 0, true><<<dim3(64, 3), 128>>>(nullptr, g_tx_p, g_dbl_p, conv_w, conv_b);
    scan_kernel<<<192, 256>>>(A_log, D_skip, dt_proj_w, dt_proj_b);
    gemm64<DIN, 192, 192, 2, false><<<dim3(64, 3), 128>>>(g_y_p, g_tout_p, out, nullptr, nullptr);
    ca_scale_kernel<<<Bn * 32, 256>>>(ca_w1, ca_b1, ca_w2, ca_b2, out);
}

// round 15
// speedup vs baseline: 1.0375x; 1.0375x over previous
#include <cuda_runtime.h>
#include <math.h>
#include <stdint.h>

#define Bn 4
#define Cc 192
#define Dd 4
#define Hh 16
#define Ww 16
#define LL 1024
#define DIN 384
#define DSTATE 64
#define DTRANK 12
#define DCONV 4
#define MM (Bn * LL)          // 4096
#define HIDN (Bn * LL * 48)   // 196608

// ---------------- scratch ----------------
__device__ float g_pooled[Bn * Cc];
__device__ float g_hidp[27 * HIDN];
__device__ float g_hidT[HIDN];          // [bl][48]
__device__ float g_offs[Bn * LL * 3];
__device__ float g_xs[MM * Cc];
__device__ float g_xz[MM * 2 * DIN];
__device__ float g_xi[MM * DIN];
__device__ float g_dbl[MM * 140];
__device__ float g_delta[MM * DIN];
__device__ float g_y[MM * DIN];
__device__ float g_p2p[Bn * 16 * Cc];
__device__ float g_xT[MM * Cc];         // [bl][c]
// pre-transposed weights [K][N]
__device__ float g_tin[Cc * 768];
__device__ float g_tcat[Cc * Cc];
__device__ float g_bcat[Cc];
__device__ float g_tx[DIN * 192];       // x_proj padded 140->192
__device__ float g_tout[DIN * Cc];
__device__ float g_tw1[27 * Cc * 48];   // conv1 [tap][c][o] unpadded

__device__ __forceinline__ float sigmoidf_(float x) { return 1.f / (1.f + expf(-x)); }
__device__ __forceinline__ float geluf_(float x) {
    return 0.5f * x * (1.f + erff(x * 0.70710678118654752440f));
}
__device__ __forceinline__ float softplusf_(float x) {
    return (x > 20.f) ? x : log1pf(expf(x));
}

// ---------------- merged prep (weight transposes) + x transpose + pooled mean ----------------
#define PREP_TOTAL (147456 + 36864 + 192 + 73728 + 73728 + 248832)
#define PREP_BLKS ((PREP_TOTAL + 255) / 256)
__global__ void prepxt_kernel(const float* __restrict__ x,
                              const float* __restrict__ in_proj_w,
                              const float* __restrict__ px_w, const float* __restrict__ py_w,
                              const float* __restrict__ pz_w,
                              const float* __restrict__ px_b, const float* __restrict__ py_b,
                              const float* __restrict__ pz_b,
                              const float* __restrict__ x_proj_w,
                              const float* __restrict__ out_proj_w,
                              const float* __restrict__ off_w1) {
    int bx = blockIdx.x;
    if (bx < 768) {
        __shared__ float tile[32][33];
        int l0 = (bx & 31) * 32;
        int c0 = ((bx >> 5) % 6) * 32;
        int b = bx / 192;
        int tx = threadIdx.x & 31, ty = threadIdx.x >> 5;
        #pragma unroll
        for (int i = 0; i < 32; i += 8)
            tile[ty + i][tx] = x[(b * Cc + c0 + ty + i) * LL + l0 + tx];
        __syncthreads();
        #pragma unroll
        for (int i = 0; i < 32; i += 8)
            g_xT[(b * LL + l0 + ty + i) * Cc + c0 + tx] = tile[tx][ty + i];
        return;
    }
    if (bx < 1536) {
        __shared__ float sm[256];
        int bc = bx - 768;
        const float* p = x + bc * LL;
        float s = 0.f;
        for (int i = threadIdx.x; i < LL; i += 256) s += p[i];
        sm[threadIdx.x] = s; __syncthreads();
        for (int st = 128; st > 0; st >>= 1) {
            if (threadIdx.x < st) sm[threadIdx.x] += sm[threadIdx.x + st];
            __syncthreads();
        }
        if (threadIdx.x == 0) g_pooled[bc] = sm[0] * (1.f / (float)LL);
        return;
    }
    int t = (bx - 1536) * 256 + threadIdx.x;
    if (t < 147456) { int k = t / 768, n = t % 768; g_tin[t] = in_proj_w[n * Cc + k]; return; }
    t -= 147456;
    if (t < 36864) {
        int k = t / Cc, n = t % Cc; int br = n >> 6, oo = n & 63;
        const float* s = (br == 0) ? px_w : (br == 1) ? py_w : pz_w;
        g_tcat[t] = s[oo * Cc + k]; return;
    }
    t -= 36864;
    if (t < Cc) {
        const float* s = (t < 64) ? px_b : (t < 128) ? py_b : pz_b;
        g_bcat[t] = s[t & 63]; return;
    }
    t -= Cc;
    if (t < 73728) { int k = t / 192, n = t % 192;
        g_tx[t] = (n < 140) ? x_proj_w[n * DIN + k] : 0.f; return; }
    t -= 73728;
    if (t < 73728) { int k = t / Cc, n = t % Cc; g_tout[t] = out_proj_w[n * DIN + k]; return; }
    t -= 73728;
    if (t < 248832) {
        int tap = t / (Cc * 48); int rem = t % (Cc * 48); int c = rem / 48, o = rem % 48;
        g_tw1[t] = off_w1[(o * Cc + c) * 27 + tap]; return;
    }
}

// ---------------- conv1 implicit GEMM, unpadded N=48: grid (64 m-tiles, 27 taps) ----------------
__global__ void conv1_kernel() {
    __shared__ float sA[64][66];
    __shared__ float sW[64][56];
    int m0 = blockIdx.x * 64;
    int tap = blockIdx.y;
    int kd = tap / 9, kh = (tap / 3) % 3, kw = tap % 3;
    int loff = (kd - 1) * 256 + (kh - 1) * 16 + (kw - 1);
    int tid = threadIdx.x;
    int tn = tid & 7, tm = tid >> 3;
    float acc[4][6] = {};
    for (int k0 = 0; k0 < Cc; k0 += 64) {
        #pragma unroll
        for (int t = 0; t < 16; ++t) {
            int idx = tid + t * 128;
            int r = idx >> 5, c2 = idx & 31;
            int ll = (m0 & 1023) + r;
            int z = ll >> 8, y = (ll >> 4) & 15, xx = ll & 15;
            bool ok = ((unsigned)(z + kd - 1) < 4u) && ((unsigned)(y + kh - 1) < 16u)
                   && ((unsigned)(xx + kw - 1) < 16u);
            float2 v = make_float2(0.f, 0.f);
            if (ok) v = *(const float2*)&g_xT[(m0 + r + loff) * Cc + k0 + c2 * 2];
            *(float2*)&sA[r][c2 * 2] = v;
        }
        #pragma unroll
        for (int t = 0; t < 6; ++t) {
            int idx = tid + t * 128;
            int r = idx / 12, c4 = idx % 12;
            *(float4*)&sW[r][c4 * 4] = *(const float4*)&g_tw1[(tap * Cc + k0 + r) * 48 + c4 * 4];
        }
        __syncthreads();
        #pragma unroll
        for (int k = 0; k < 64; ++k) {
            float a0 = sA[tm * 4 + 0][k], a1 = sA[tm * 4 + 1][k];
            float a2 = sA[tm * 4 + 2][k], a3 = sA[tm * 4 + 3][k];
            float4 wlo = *(const float4*)&sW[k][tn * 4];
            float2 whi = *(const float2*)&sW[k][32 + tn * 2];
            acc[0][0] += a0*wlo.x; acc[0][1] += a0*wlo.y; acc[0][2] += a0*wlo.z;
            acc[0][3] += a0*wlo.w; acc[0][4] += a0*whi.x; acc[0][5] += a0*whi.y;
            acc[1][0] += a1*wlo.x; acc[1][1] += a1*wlo.y; acc[1][2] += a1*wlo.z;
            acc[1][3] += a1*wlo.w; acc[1][4] += a1*whi.x; acc[1][5] += a1*whi.y;
            acc[2][0] += a2*wlo.x; acc[2][1] += a2*wlo.y; acc[2][2] += a2*wlo.z;
            acc[2][3] += a2*wlo.w; acc[2][4] += a2*whi.x; acc[2][5] += a2*whi.y;
            acc[3][0] += a3*wlo.x; acc[3][1] += a3*wlo.y; acc[3][2] += a3*wlo.z;
            acc[3][3] += a3*wlo.w; acc[3][4] += a3*whi.x; acc[3][5] += a3*whi.y;
        }
        __syncthreads();
    }
    float* dst = g_hidp + tap * HIDN;
    #pragma unroll
    for (int i = 0; i < 4; ++i) {
        int l = m0 + tm * 4 + i;
        *(float4*)&dst[l * 48 + tn * 4] =
            make_float4(acc[i][0], acc[i][1], acc[i][2], acc[i][3]);
        *(float2*)&dst[l * 48 + 32 + tn * 2] = make_float2(acc[i][4], acc[i][5]);
    }
}

// ---------------- reduce 27 partials + bias + gelu (float4) ----------------
__global__ void hidred_kernel(const float* __restrict__ b1) {
    int t = blockIdx.x * 256 + threadIdx.x;
    if (t >= HIDN / 4) return;
    int o4 = t % 12;
    float4 s = *(const float4*)&b1[o4 * 4];
    #pragma unroll
    for (int k = 0; k < 27; ++k) {
        float4 v = *(const float4*)&g_hidp[k * HIDN + t * 4];
        s.x += v.x; s.y += v.y; s.z += v.z; s.w += v.w;
    }
    float4 r = make_float4(geluf_(s.x), geluf_(s.y), geluf_(s.z), geluf_(s.w));
    *(float4*)&g_hidT[t * 4] = r;
}

// ---------------- conv2: one warp per voxel, 8 warps/block ----------------
__global__ void conv2_kernel(const float* __restrict__ w2, const float* __restrict__ b2) {
    __shared__ float ws[3 * 48 * 27];
    int tid = threadIdx.x;
    for (int i = tid; i < 3 * 48 * 27; i += 256) ws[i] = w2[i];
    __syncthreads();
    int lane = tid & 31, warpid = tid >> 5;
    int bl = blockIdx.x * 8 + warpid;
    int ll = bl & 1023;
    int z = ll >> 8, y = (ll >> 4) & 15, xx = ll & 15;
    int c2 = 32 + (lane & 15);
    float m2 = (lane < 16) ? 1.f : 0.f;
    float s0 = 0.f, s1 = 0.f, s2 = 0.f;
    #pragma unroll
    for (int tap = 0; tap < 27; ++tap) {
        int kd = tap / 9, kh = (tap / 3) % 3, kw = tap % 3;
        bool ok = ((unsigned)(z + kd - 1) < 4u) && ((unsigned)(y + kh - 1) < 16u)
               && ((unsigned)(xx + kw - 1) < 16u);
        if (ok) {
            int bl2 = bl + (kd - 1) * 256 + (kh - 1) * 16 + (kw - 1);
            float h0 = g_hidT[bl2 * 48 + lane];
            float h1 = m2 * g_hidT[bl2 * 48 + c2 - ((lane < 16) ? 0 : 16)];
            s0 += h0 * ws[(0 * 48 + lane) * 27 + tap] + h1 * ws[(0 * 48 + c2) * 27 + tap];
            s1 += h0 * ws[(1 * 48 + lane) * 27 + tap] + h1 * ws[(1 * 48 + c2) * 27 + tap];
            s2 += h0 * ws[(2 * 48 + lane) * 27 + tap] + h1 * ws[(2 * 48 + c2) * 27 + tap];
        }
    }
    #pragma unroll
    for (int off = 16; off; off >>= 1) {
        s0 += __shfl_xor_sync(0xffffffffu, s0, off);
        s1 += __shfl_xor_sync(0xffffffffu, s1, off);
        s2 += __shfl_xor_sync(0xffffffffu, s2, off);
    }
    if (lane == 0) {
        g_offs[bl * 3 + 0] = s0 + b2[0];
        g_offs[bl * 3 + 1] = s1 + b2[1];
        g_offs[bl * 3 + 2] = s2 + b2[2];
    }
}

// ---------------- conflict-free tiled GEMM ----------------
// EPI 0: plain (guard NR)
// EPI 1: g_xs = (acc+bias)*softmax-gate + posemb-gather
// EPI 2: transposed out + per-tile partial channel means into g_p2p
template<int K, int NP, int NR, int EPI>
__global__ void gemm64(const float* __restrict__ A, const float* __restrict__ Wt,
                       float* __restrict__ outp,
                       const float* __restrict__ wg_w, const float* __restrict__ wg_b) {
    __shared__ float sA[64][66];
    __shared__ float sW[64][72];
    __shared__ float slg[3];
    int m0 = blockIdx.x * 64;
    int n0 = blockIdx.y * 64;
    int tid = threadIdx.x;
    int tn = tid & 7, tm = tid >> 3;
    if (EPI == 1) {
        int warpid = tid >> 5, lane = tid & 31;
        if (warpid < 3) {
            int b = m0 >> 10;
            float s = 0.f;
            for (int c = lane; c < Cc; c += 32) s += g_pooled[b * Cc + c] * wg_w[warpid * Cc + c];
            #pragma unroll
            for (int off = 16; off; off >>= 1) s += __shfl_xor_sync(0xffffffffu, s, off);
            if (lane == 0) slg[warpid] = s + wg_b[warpid];
        }
    }
    float acc[4][8] = {};
    for (int k0 = 0; k0 < K; k0 += 64) {
        #pragma unroll
        for (int t = 0; t < 16; ++t) {
            int idx = tid + t * 128;
            int r = idx >> 5, c2 = idx & 31;
            *(float2*)&sA[r][c2 * 2] = *(const float2*)&A[(m0 + r) * K + k0 + c2 * 2];
        }
        #pragma unroll
        for (int t = 0; t < 8; ++t) {
            int idx = tid + t * 128;
            int r = idx >> 4, c4 = idx & 15;
            *(float4*)&sW[r][c4 * 4] = *(const float4*)&Wt[(k0 + r) * NP + n0 + c4 * 4];
        }
        __syncthreads();
        #pragma unroll
        for (int k = 0; k < 64; ++k) {
            float a0 = sA[tm * 4 + 0][k], a1 = sA[tm * 4 + 1][k];
            float a2 = sA[tm * 4 + 2][k], a3 = sA[tm * 4 + 3][k];
            float4 wlo = *(const float4*)&sW[k][tn * 4];
            float4 whi = *(const float4*)&sW[k][32 + tn * 4];
            acc[0][0] += a0*wlo.x; acc[0][1] += a0*wlo.y; acc[0][2] += a0*wlo.z; acc[0][3] += a0*wlo.w;
            acc[0][4] += a0*whi.x; acc[0][5] += a0*whi.y; acc[0][6] += a0*whi.z; acc[0][7] += a0*whi.w;
            acc[1][0] += a1*wlo.x; acc[1][1] += a1*wlo.y; acc[1][2] += a1*wlo.z; acc[1][3] += a1*wlo.w;
            acc[1][4] += a1*whi.x; acc[1][5] += a1*whi.y; acc[1][6] += a1*whi.z; acc[1][7] += a1*whi.w;
            acc[2][0] += a2*wlo.x; acc[2][1] += a2*wlo.y; acc[2][2] += a2*wlo.z; acc[2][3] += a2*wlo.w;
            acc[2][4] += a2*whi.x; acc[2][5] += a2*whi.y; acc[2][6] += a2*whi.z; acc[2][7] += a2*whi.w;
            acc[3][0] += a3*wlo.x; acc[3][1] += a3*wlo.y; acc[3][2] += a3*wlo.z; acc[3][3] += a3*wlo.w;
            acc[3][4] += a3*whi.x; acc[3][5] += a3*whi.y; acc[3][6] += a3*whi.z; acc[3][7] += a3*whi.w;
        }
        __syncthreads();
    }
    if (EPI == 0) {
        #pragma unroll
        for (int i = 0; i < 4; ++i) {
            int l = m0 + tm * 4 + i;
            if (NP == NR) {
                *(float4*)&outp[l * NR + n0 + tn * 4] =
                    make_float4(acc[i][0], acc[i][1], acc[i][2], acc[i][3]);
                *(float4*)&outp[l * NR + n0 + 32 + tn * 4] =
                    make_float4(acc[i][4], acc[i][5], acc[i][6], acc[i][7]);
            } else {
                #pragma unroll
                for (int j = 0; j < 4; ++j) {
                    int n = n0 + tn * 4 + j;
                    if (n < NR) outp[l * NR + n] = acc[i][j];
                    int n2 = n0 + 32 + tn * 4 + j;
                    if (n2 < NR) outp[l * NR + n2] = acc[i][j + 4];
                }
            }
        }
    } else if (EPI == 1) {
        float mx = fmaxf(slg[0], fmaxf(slg[1], slg[2]));
        float e0 = expf(slg[0] - mx), e1 = expf(slg[1] - mx), e2 = expf(slg[2] - mx);
        int br = n0 >> 6;
        float wt = ((br == 0) ? e0 : (br == 1) ? e1 : e2) / (e0 + e1 + e2);
        int b = m0 >> 10;
        #pragma unroll
        for (int i = 0; i < 4; ++i) {
            int l = m0 + tm * 4 + i;
            float gx = g_offs[l * 3 + 0];
            float gy = g_offs[l * 3 + 1];
            float gz = g_offs[l * 3 + 2];
            float ixf = ((gx + 1.f) * (float)Ww - 1.f) * 0.5f;
            float iyf = ((gy + 1.f) * (float)Hh - 1.f) * 0.5f;
            float izf = ((gz + 1.f) * (float)Dd - 1.f) * 0.5f;
            float x0f = floorf(ixf), y0f = floorf(iyf), z0f = floorf(izf);
            int idxs[8]; float w8[8];
            int corner = 0;
            #pragma unroll
            for (int dz = 0; dz < 2; ++dz)
            #pragma unroll
            for (int dy = 0; dy < 2; ++dy)
            #pragma unroll
            for (int dx = 0; dx < 2; ++dx) {
                float xc = x0f + dx, yc = y0f + dy, zc = z0f + dz;
                float wg = (1.f - fabsf(ixf - xc)) * (1.f - fabsf(iyf - yc))
                         * (1.f - fabsf(izf - zc));
                bool valid = (xc >= 0.f) && (xc < (float)Ww) && (yc >= 0.f)
                          && (yc < (float)Hh) && (zc >= 0.f) && (zc < (float)Dd);
                int xi_ = (int)fminf(fmaxf(xc, 0.f), (float)(Ww - 1));
                int yi_ = (int)fminf(fmaxf(yc, 0.f), (float)(Hh - 1));
                int zi_ = (int)fminf(fmaxf(zc, 0.f), (float)(Dd - 1));
                idxs[corner] = b * LL + (zi_ * Hh + yi_) * Ww + xi_;
                w8[corner] = wg * (valid ? 1.f : 0.f);
                ++corner;
            }
            #pragma unroll
            for (int j = 0; j < 4; ++j) {
                int c1 = n0 + tn * 4 + j;
                int c2 = n0 + 32 + tn * 4 + j;
                float pe1 = 0.f, pe2 = 0.f;
                #pragma unroll
                for (int k = 0; k < 8; ++k) {
                    pe1 += g_xT[idxs[k] * Cc + c1] * w8[k];
                    pe2 += g_xT[idxs[k] * Cc + c2] * w8[k];
                }
                outp[l * Cc + c1] = (acc[i][j] + g_bcat[c1]) * wt + pe1;
                outp[l * Cc + c2] = (acc[i][j + 4] + g_bcat[c2]) * wt + pe2;
            }
        }
    } else {
        float* sT = &sW[0][0];
        #pragma unroll
        for (int i = 0; i < 4; ++i) {
            int ml = tm * 4 + i;
            #pragma unroll
            for (int j = 0; j < 4; ++j) {
                sT[(tn * 4 + j) * 68 + ml] = acc[i][j];
                sT[(32 + tn * 4 + j) * 68 + ml] = acc[i][j + 4];
            }
        }
        __syncthreads();
        int b = m0 >> 10, l0 = m0 & 1023;
        #pragma unroll
        for (int t = 0; t < 8; ++t) {
            int idx = tid + t * 128;
            int nr = idx >> 4, c4 = idx & 15;
            float4 v = *(const float4*)&sT[nr * 68 + c4 * 4];
            *(float4*)&outp[((b * Cc + n0 + nr) << 10) + l0 + c4 * 4] = v;
        }
        if (tid < 64) {
            float s = 0.f;
            #pragma unroll 8
            for (int ll = 0; ll < 64; ++ll) s += sT[tid * 68 + ll];
            int ltile = (m0 & 1023) >> 6;
            g_p2p[(b * 16 + ltile) * Cc + n0 + tid] = s;
        }
    }
}

// ---------------- depthwise causal conv + silu (float4 over d) ----------------
__global__ void dwconv_kernel(const float* __restrict__ cw, const float* __restrict__ cb) {
    int v = blockIdx.x * 256 + threadIdx.x;
    if (v >= MM * 96) return;
    int d4 = (v % 96) * 4;
    int bl = v / 96;
    int l = bl & 1023, b = bl >> 10;
    const float* base = g_xz + (b * LL) * (2 * DIN) + d4;
    float4 s = *(const float4*)&cb[d4];
    float4 w0 = *(const float4*)&cw[(d4 + 0) * DCONV];
    float4 w1 = *(const float4*)&cw[(d4 + 1) * DCONV];
    float4 w2 = *(const float4*)&cw[(d4 + 2) * DCONV];
    float4 w3 = *(const float4*)&cw[(d4 + 3) * DCONV];
    const float* wk0 = (const float*)&w0;
    const float* wk1 = (const float*)&w1;
    const float* wk2 = (const float*)&w2;
    const float* wk3 = (const float*)&w3;
    #pragma unroll
    for (int k = 0; k < DCONV; ++k) {
        int ll = l - (DCONV - 1) + k;
        if (ll >= 0) {
            float4 xv = *(const float4*)&base[ll * (2 * DIN)];
            s.x += xv.x * wk0[k];
            s.y += xv.y * wk1[k];
            s.z += xv.z * wk2[k];
            s.w += xv.w * wk3[k];
        }
    }
    float4 r;
    r.x = s.x * sigmoidf_(s.x);
    r.y = s.y * sigmoidf_(s.y);
    r.z = s.z * sigmoidf_(s.z);
    r.w = s.w * sigmoidf_(s.w);
    *(float4*)&g_xi[bl * DIN + d4] = r;
}

// ---------------- delta (float4 over d, shared row loads) ----------------
__global__ void delta_kernel(const float* __restrict__ dtw, const float* __restrict__ dtb) {
    __shared__ float sdt[DIN * DTRANK];
    int tid = threadIdx.x;
    for (int k = tid; k < DIN * DTRANK; k += 256) sdt[k] = dtw[k];
    __syncthreads();
    int v = blockIdx.x * 256 + tid;
    if (v >= MM * 96) return;
    int d4 = (v % 96) * 4;
    int bl = v / 96;
    const float* row = g_dbl + bl * 140;
    float rr[DTRANK];
    #pragma unroll
    for (int r = 0; r < DTRANK; ++r) rr[r] = __ldg(row + r);
    float4 s = *(const float4*)&dtb[d4];
    #pragma unroll
    for (int r = 0; r < DTRANK; ++r) {
        s.x += rr[r] * sdt[(d4 + 0) * DTRANK + r];
        s.y += rr[r] * sdt[(d4 + 1) * DTRANK + r];
        s.z += rr[r] * sdt[(d4 + 2) * DTRANK + r];
        s.w += rr[r] * sdt[(d4 + 3) * DTRANK + r];
    }
    float4 o;
    o.x = softplusf_(s.x); o.y = softplusf_(s.y);
    o.z = softplusf_(s.z); o.w = softplusf_(s.w);
    *(float4*)&g_delta[bl * DIN + d4] = o;
}

// ---------------- selective scan: warp per (b,d), batched transposed reduction ----------------
__global__ void scan_kernel(const float* __restrict__ a_log, const float* __restrict__ Dskip) {
    __shared__ float sm[8][32][33];
    int wIn = threadIdx.x >> 5, lane = threadIdx.x & 31;
    int bd = blockIdx.x * 8 + wIn;
    int b = bd / DIN, d = bd % DIN;
    float (*S)[33] = sm[wIn];
    float a0 = -expf(a_log[d * DSTATE + lane]);
    float a1 = -expf(a_log[d * DSTATE + 32 + lane]);
    float dsk = Dskip[d];
    float h0 = 0.f, h1 = 0.f;
    const float* dptr = g_delta + b * LL * DIN + d;
    const float* uptr = g_xi + b * LL * DIN + d;
    const float* dblb = g_dbl + b * LL * 140;
    const float* zbase = g_xz + b * LL * (2 * DIN) + DIN + d;
    float* yo = g_y + b * LL * DIN + d;
    for (int l0 = 0; l0 < LL; l0 += 32) {
        #pragma unroll 4
        for (int j = 0; j < 32; ++j) {
            int l = l0 + j;
            float dt = __ldg(dptr + l * DIN);
            float u = __ldg(uptr + l * DIN);
            const float* row = dblb + l * 140;
            float b0 = __ldg(row + 12 + lane), b1v = __ldg(row + 44 + lane);
            float c0 = __ldg(row + 76 + lane), c1 = __ldg(row + 108 + lane);
            float du = dt * u;
            h0 = __expf(dt * a0) * h0 + du * b0;
            h1 = __expf(dt * a1) * h1 + du * b1v;
            S[j][lane] = h0 * c0 + h1 * c1;
        }
        __syncwarp();
        float s = 0.f;
        #pragma unroll
        for (int k = 0; k < 32; ++k) s += S[lane][k];
        int l = l0 + lane;
        float u2 = __ldg(uptr + l * DIN);
        float z = __ldg(zbase + l * (2 * DIN));
        yo[l * DIN] = (s + u2 * dsk) * (z * sigmoidf_(z));
        __syncwarp();
    }
}

// ---------------- fused channel attention + scale (with partial-mean reduce) ----------------
__global__ void ca_scale_kernel(const float* __restrict__ w1, const float* __restrict__ b1,
                                const float* __restrict__ w2, const float* __restrict__ b2,
                                float* __restrict__ out) {
    int b = blockIdx.x >> 5;
    int chunk = blockIdx.x & 31;
    int tid = threadIdx.x;
    __shared__ float p[Cc];
    __shared__ float hid[48];
    __shared__ float attn[Cc];
    if (tid < Cc) {
        float s = 0.f;
        #pragma unroll
        for (int t = 0; t < 16; ++t) s += g_p2p[(b * 16 + t) * Cc + tid];
        p[tid] = s * (1.f / (float)LL);
    }
    __syncthreads();
    if (tid < 48) {
        const float* wr = w1 + tid * Cc;
        float s = b1[tid];
        #pragma unroll 8
        for (int k = 0; k < Cc; ++k) s += p[k] * wr[k];
        hid[tid] = geluf_(s);
    }
    __syncthreads();
    if (tid < Cc) {
        const float* wr2 = w2 + tid * 48;
        float s = b2[tid];
        #pragma unroll
        for (int j = 0; j < 48; ++j) s += hid[j] * wr2[j];
        attn[tid] = sigmoidf_(s);
    }
    __syncthreads();
    int l0 = chunk * 32;
    for (int e = tid; e < Cc * 32; e += 256) {
        int c = e >> 5, l = l0 + (e & 31);
        out[(b * Cc + c) * LL + l] *= attn[c];
    }
}

extern "C" void kernel_launch(void* const* d_in, const int* in_sizes, int n_in,
                              void* d_out, int out_size) {
    const float* x         = (const float*)d_in[0];
    const float* px_w      = (const float*)d_in[1];
    const float* px_b      = (const float*)d_in[2];
    const float* py_w      = (const float*)d_in[3];
    const float* py_b      = (const float*)d_in[4];
    const float* pz_w      = (const float*)d_in[5];
    const float* pz_b      = (const float*)d_in[6];
    const float* wg_w      = (const float*)d_in[7];
    const float* wg_b      = (const float*)d_in[8];
    const float* off_w1    = (const float*)d_in[9];
    const float* off_b1    = (const float*)d_in[10];
    const float* off_w2    = (const float*)d_in[11];
    const float* off_b2    = (const float*)d_in[12];
    const float* in_proj_w = (const float*)d_in[13];
    const float* conv_w    = (const float*)d_in[14];
    const float* conv_b    = (const float*)d_in[15];
    const float* x_proj_w  = (const float*)d_in[16];
    const float* dt_proj_w = (const float*)d_in[17];
    const float* dt_proj_b = (const float*)d_in[18];
    const float* A_log     = (const float*)d_in[19];
    const float* D_skip    = (const float*)d_in[20];
    const float* out_proj_w = (const float*)d_in[21];
    const float* ca_w1     = (const float*)d_in[22];
    const float* ca_b1     = (const float*)d_in[23];
    const float* ca_w2     = (const float*)d_in[24];
    const float* ca_b2     = (const float*)d_in[25];
    float* out = (float*)d_out;

    float *g_xT_p, *g_xs_p, *g_xz_p, *g_xi_p, *g_dbl_p, *g_y_p;
    float *g_tin_p, *g_tcat_p, *g_tx_p, *g_tout_p;
    cudaGetSymbolAddress((void**)&g_xT_p, g_xT);
    cudaGetSymbolAddress((void**)&g_xs_p, g_xs);
    cudaGetSymbolAddress((void**)&g_xz_p, g_xz);
    cudaGetSymbolAddress((void**)&g_xi_p, g_xi);
    cudaGetSymbolAddress((void**)&g_dbl_p, g_dbl);
    cudaGetSymbolAddress((void**)&g_y_p, g_y);
    cudaGetSymbolAddress((void**)&g_tin_p, g_tin);
    cudaGetSymbolAddress((void**)&g_tcat_p, g_tcat);
    cudaGetSymbolAddress((void**)&g_tx_p, g_tx);
    cudaGetSymbolAddress((void**)&g_tout_p, g_tout);

    prepxt_kernel<<<1536 + PREP_BLKS, 256>>>(x, in_proj_w, px_w, py_w, pz_w,
                                             px_b, py_b, pz_b, x_proj_w, out_proj_w, off_w1);
    conv1_kernel<<<dim3(64, 27), 128>>>();
    hidred_kernel<<<(HIDN / 4 + 255) / 256, 256>>>(off_b1);
    conv2_kernel<<<MM / 8, 256>>>(off_w2, off_b2);
    gemm64<Cc, Cc, Cc, 1><<<dim3(64, 3), 128>>>(g_xT_p, g_tcat_p, g_xs_p, wg_w, wg_b);
    gemm64<Cc, 768, 768, 0><<<dim3(64, 12), 128>>>(g_xs_p, g_tin_p, g_xz_p, nullptr, nullptr);
    dwconv_kernel<<<(MM * 96 + 255) / 256, 256>>>(conv_w, conv_b);
    gemm64<DIN, 192, 140, 0><<<dim3(64, 3), 128>>>(g_xi_p, g_tx_p, g_dbl_p, nullptr, nullptr);
    delta_kernel<<<(MM * 96 + 255) / 256, 256>>>(dt_proj_w, dt_proj_b);
    scan_kernel<<<192, 256>>>(A_log, D_skip);
    gemm64<DIN, 192, 192, 2><<<dim3(64, 3), 128>>>(g_y_p, g_tout_p, out, nullptr, nullptr);
    ca_scale_kernel<<<Bn * 32, 256>>>(ca_w1, ca_b1, ca_w2, ca_b2, out);
}

// round 16
// speedup vs baseline: 1.2545x; 1.2092x over previous
#include <cuda_runtime.h>
#include <math.h>
#include <stdint.h>

#define Bn 4
#define Cc 192
#define Dd 4
#define Hh 16
#define Ww 16
#define LL 1024
#define DIN 384
#define DSTATE 64
#define DTRANK 12
#define DCONV 4
#define MM (Bn * LL)          // 4096
#define HIDN (Bn * LL * 48)   // 196608

// ---------------- scratch ----------------
__device__ float g_pooled[Bn * Cc];
__device__ float g_hidp[27 * HIDN];
__device__ float g_hidT[HIDN];          // [bl][48]
__device__ float g_offs[Bn * LL * 3];
__device__ float g_xs[MM * Cc];
__device__ float g_xz[MM * 2 * DIN];
__device__ float g_xi[MM * DIN];
__device__ float g_dbl[MM * 140];
__device__ float g_delta[MM * DIN];
__device__ float g_y[MM * DIN];
__device__ float g_p2p[Bn * 16 * Cc];
__device__ float g_xT[MM * Cc];         // [bl][c]
// pre-transposed weights [K][N]
__device__ float g_tin[Cc * 768];
__device__ float g_tcat[Cc * Cc];
__device__ float g_bcat[Cc];
__device__ float g_tx[DIN * 192];       // x_proj padded 140->192
__device__ float g_tout[DIN * Cc];
__device__ float g_tw1[27 * Cc * 48];   // conv1 [tap][c][o] unpadded

__device__ __forceinline__ float sigmoidf_(float x) { return 1.f / (1.f + expf(-x)); }
__device__ __forceinline__ float geluf_(float x) {
    return 0.5f * x * (1.f + erff(x * 0.70710678118654752440f));
}
__device__ __forceinline__ float softplusf_(float x) {
    return (x > 20.f) ? x : log1pf(expf(x));
}

// ---------------- merged prep (weight transposes) + x transpose + pooled mean ----------------
#define PREP_TOTAL (147456 + 36864 + 192 + 73728 + 73728 + 248832)
#define PREP_BLKS ((PREP_TOTAL + 255) / 256)
__global__ void prepxt_kernel(const float* __restrict__ x,
                              const float* __restrict__ in_proj_w,
                              const float* __restrict__ px_w, const float* __restrict__ py_w,
                              const float* __restrict__ pz_w,
                              const float* __restrict__ px_b, const float* __restrict__ py_b,
                              const float* __restrict__ pz_b,
                              const float* __restrict__ x_proj_w,
                              const float* __restrict__ out_proj_w,
                              const float* __restrict__ off_w1) {
    int bx = blockIdx.x;
    if (bx < 768) {
        __shared__ float tile[32][33];
        int l0 = (bx & 31) * 32;
        int c0 = ((bx >> 5) % 6) * 32;
        int b = bx / 192;
        int tx = threadIdx.x & 31, ty = threadIdx.x >> 5;
        #pragma unroll
        for (int i = 0; i < 32; i += 8)
            tile[ty + i][tx] = x[(b * Cc + c0 + ty + i) * LL + l0 + tx];
        __syncthreads();
        #pragma unroll
        for (int i = 0; i < 32; i += 8)
            g_xT[(b * LL + l0 + ty + i) * Cc + c0 + tx] = tile[tx][ty + i];
        return;
    }
    if (bx < 1536) {
        __shared__ float sm[256];
        int bc = bx - 768;
        const float* p = x + bc * LL;
        float s = 0.f;
        for (int i = threadIdx.x; i < LL; i += 256) s += p[i];
        sm[threadIdx.x] = s; __syncthreads();
        for (int st = 128; st > 0; st >>= 1) {
            if (threadIdx.x < st) sm[threadIdx.x] += sm[threadIdx.x + st];
            __syncthreads();
        }
        if (threadIdx.x == 0) g_pooled[bc] = sm[0] * (1.f / (float)LL);
        return;
    }
    int t = (bx - 1536) * 256 + threadIdx.x;
    if (t < 147456) { int k = t / 768, n = t % 768; g_tin[t] = in_proj_w[n * Cc + k]; return; }
    t -= 147456;
    if (t < 36864) {
        int k = t / Cc, n = t % Cc; int br = n >> 6, oo = n & 63;
        const float* s = (br == 0) ? px_w : (br == 1) ? py_w : pz_w;
        g_tcat[t] = s[oo * Cc + k]; return;
    }
    t -= 36864;
    if (t < Cc) {
        const float* s = (t < 64) ? px_b : (t < 128) ? py_b : pz_b;
        g_bcat[t] = s[t & 63]; return;
    }
    t -= Cc;
    if (t < 73728) { int k = t / 192, n = t % 192;
        g_tx[t] = (n < 140) ? x_proj_w[n * DIN + k] : 0.f; return; }
    t -= 73728;
    if (t < 73728) { int k = t / Cc, n = t % Cc; g_tout[t] = out_proj_w[n * DIN + k]; return; }
    t -= 73728;
    if (t < 248832) {
        int tap = t / (Cc * 48); int rem = t % (Cc * 48); int c = rem / 48, o = rem % 48;
        g_tw1[t] = off_w1[(o * Cc + c) * 27 + tap]; return;
    }
}

// ---------------- conv1 implicit GEMM, unpadded N=48: grid (64 m-tiles, 27 taps) ----------------
__global__ void conv1_kernel() {
    __shared__ float sA[64][66];
    __shared__ float sW[64][56];
    int m0 = blockIdx.x * 64;
    int tap = blockIdx.y;
    int kd = tap / 9, kh = (tap / 3) % 3, kw = tap % 3;
    int loff = (kd - 1) * 256 + (kh - 1) * 16 + (kw - 1);
    int tid = threadIdx.x;
    int tn = tid & 7, tm = tid >> 3;
    float acc[4][6] = {};
    for (int k0 = 0; k0 < Cc; k0 += 64) {
        #pragma unroll
        for (int t = 0; t < 16; ++t) {
            int idx = tid + t * 128;
            int r = idx >> 5, c2 = idx & 31;
            int ll = (m0 & 1023) + r;
            int z = ll >> 8, y = (ll >> 4) & 15, xx = ll & 15;
            bool ok = ((unsigned)(z + kd - 1) < 4u) && ((unsigned)(y + kh - 1) < 16u)
                   && ((unsigned)(xx + kw - 1) < 16u);
            float2 v = make_float2(0.f, 0.f);
            if (ok) v = *(const float2*)&g_xT[(m0 + r + loff) * Cc + k0 + c2 * 2];
            *(float2*)&sA[r][c2 * 2] = v;
        }
        #pragma unroll
        for (int t = 0; t < 6; ++t) {
            int idx = tid + t * 128;
            int r = idx / 12, c4 = idx % 12;
            *(float4*)&sW[r][c4 * 4] = *(const float4*)&g_tw1[(tap * Cc + k0 + r) * 48 + c4 * 4];
        }
        __syncthreads();
        #pragma unroll
        for (int k = 0; k < 64; ++k) {
            float a0 = sA[tm * 4 + 0][k], a1 = sA[tm * 4 + 1][k];
            float a2 = sA[tm * 4 + 2][k], a3 = sA[tm * 4 + 3][k];
            float4 wlo = *(const float4*)&sW[k][tn * 4];
            float2 whi = *(const float2*)&sW[k][32 + tn * 2];
            acc[0][0] += a0*wlo.x; acc[0][1] += a0*wlo.y; acc[0][2] += a0*wlo.z;
            acc[0][3] += a0*wlo.w; acc[0][4] += a0*whi.x; acc[0][5] += a0*whi.y;
            acc[1][0] += a1*wlo.x; acc[1][1] += a1*wlo.y; acc[1][2] += a1*wlo.z;
            acc[1][3] += a1*wlo.w; acc[1][4] += a1*whi.x; acc[1][5] += a1*whi.y;
            acc[2][0] += a2*wlo.x; acc[2][1] += a2*wlo.y; acc[2][2] += a2*wlo.z;
            acc[2][3] += a2*wlo.w; acc[2][4] += a2*whi.x; acc[2][5] += a2*whi.y;
            acc[3][0] += a3*wlo.x; acc[3][1] += a3*wlo.y; acc[3][2] += a3*wlo.z;
            acc[3][3] += a3*wlo.w; acc[3][4] += a3*whi.x; acc[3][5] += a3*whi.y;
        }
        __syncthreads();
    }
    float* dst = g_hidp + tap * HIDN;
    #pragma unroll
    for (int i = 0; i < 4; ++i) {
        int l = m0 + tm * 4 + i;
        *(float4*)&dst[l * 48 + tn * 4] =
            make_float4(acc[i][0], acc[i][1], acc[i][2], acc[i][3]);
        *(float2*)&dst[l * 48 + 32 + tn * 2] = make_float2(acc[i][4], acc[i][5]);
    }
}

// ---------------- reduce 27 partials + bias + gelu (float4) ----------------
__global__ void hidred_kernel(const float* __restrict__ b1) {
    int t = blockIdx.x * 256 + threadIdx.x;
    if (t >= HIDN / 4) return;
    int o4 = t % 12;
    float4 s = *(const float4*)&b1[o4 * 4];
    #pragma unroll
    for (int k = 0; k < 27; ++k) {
        float4 v = *(const float4*)&g_hidp[k * HIDN + t * 4];
        s.x += v.x; s.y += v.y; s.z += v.z; s.w += v.w;
    }
    float4 r = make_float4(geluf_(s.x), geluf_(s.y), geluf_(s.z), geluf_(s.w));
    *(float4*)&g_hidT[t * 4] = r;
}

// ---------------- conv2: one warp per voxel, 4 warps/block ----------------
__global__ void conv2_kernel(const float* __restrict__ w2, const float* __restrict__ b2) {
    __shared__ float ws[3 * 48 * 27];
    int tid = threadIdx.x;
    for (int i = tid; i < 3 * 48 * 27; i += 128) ws[i] = w2[i];
    __syncthreads();
    int lane = tid & 31, warpid = tid >> 5;
    int bl = blockIdx.x * 4 + warpid;
    int ll = bl & 1023;
    int z = ll >> 8, y = (ll >> 4) & 15, xx = ll & 15;
    int c2 = 32 + (lane & 15);
    float m2 = (lane < 16) ? 1.f : 0.f;
    float s0 = 0.f, s1 = 0.f, s2 = 0.f;
    #pragma unroll
    for (int tap = 0; tap < 27; ++tap) {
        int kd = tap / 9, kh = (tap / 3) % 3, kw = tap % 3;
        bool ok = ((unsigned)(z + kd - 1) < 4u) && ((unsigned)(y + kh - 1) < 16u)
               && ((unsigned)(xx + kw - 1) < 16u);
        if (ok) {
            int bl2 = bl + (kd - 1) * 256 + (kh - 1) * 16 + (kw - 1);
            float h0 = g_hidT[bl2 * 48 + lane];
            float h1 = m2 * g_hidT[bl2 * 48 + c2 - ((lane < 16) ? 0 : 16)];
            s0 += h0 * ws[(0 * 48 + lane) * 27 + tap] + h1 * ws[(0 * 48 + c2) * 27 + tap];
            s1 += h0 * ws[(1 * 48 + lane) * 27 + tap] + h1 * ws[(1 * 48 + c2) * 27 + tap];
            s2 += h0 * ws[(2 * 48 + lane) * 27 + tap] + h1 * ws[(2 * 48 + c2) * 27 + tap];
        }
    }
    #pragma unroll
    for (int off = 16; off; off >>= 1) {
        s0 += __shfl_xor_sync(0xffffffffu, s0, off);
        s1 += __shfl_xor_sync(0xffffffffu, s1, off);
        s2 += __shfl_xor_sync(0xffffffffu, s2, off);
    }
    if (lane == 0) {
        g_offs[bl * 3 + 0] = s0 + b2[0];
        g_offs[bl * 3 + 1] = s1 + b2[1];
        g_offs[bl * 3 + 2] = s2 + b2[2];
    }
}

// ---------------- conflict-free tiled GEMM ----------------
// EPI 0: plain (guard NR)
// EPI 1: g_xs = (acc+bias)*softmax-gate + posemb-gather
// EPI 2: transposed out + per-tile partial channel means into g_p2p
template<int K, int NP, int NR, int EPI>
__global__ void gemm64(const float* __restrict__ A, const float* __restrict__ Wt,
                       float* __restrict__ outp,
                       const float* __restrict__ wg_w, const float* __restrict__ wg_b) {
    __shared__ float sA[64][66];
    __shared__ float sW[64][72];
    __shared__ float slg[3];
    int m0 = blockIdx.x * 64;
    int n0 = blockIdx.y * 64;
    int tid = threadIdx.x;
    int tn = tid & 7, tm = tid >> 3;
    if (EPI == 1) {
        int warpid = tid >> 5, lane = tid & 31;
        if (warpid < 3) {
            int b = m0 >> 10;
            float s = 0.f;
            for (int c = lane; c < Cc; c += 32) s += g_pooled[b * Cc + c] * wg_w[warpid * Cc + c];
            #pragma unroll
            for (int off = 16; off; off >>= 1) s += __shfl_xor_sync(0xffffffffu, s, off);
            if (lane == 0) slg[warpid] = s + wg_b[warpid];
        }
    }
    float acc[4][8] = {};
    for (int k0 = 0; k0 < K; k0 += 64) {
        #pragma unroll
        for (int t = 0; t < 16; ++t) {
            int idx = tid + t * 128;
            int r = idx >> 5, c2 = idx & 31;
            *(float2*)&sA[r][c2 * 2] = *(const float2*)&A[(m0 + r) * K + k0 + c2 * 2];
        }
        #pragma unroll
        for (int t = 0; t < 8; ++t) {
            int idx = tid + t * 128;
            int r = idx >> 4, c4 = idx & 15;
            *(float4*)&sW[r][c4 * 4] = *(const float4*)&Wt[(k0 + r) * NP + n0 + c4 * 4];
        }
        __syncthreads();
        #pragma unroll
        for (int k = 0; k < 64; ++k) {
            float a0 = sA[tm * 4 + 0][k], a1 = sA[tm * 4 + 1][k];
            float a2 = sA[tm * 4 + 2][k], a3 = sA[tm * 4 + 3][k];
            float4 wlo = *(const float4*)&sW[k][tn * 4];
            float4 whi = *(const float4*)&sW[k][32 + tn * 4];
            acc[0][0] += a0*wlo.x; acc[0][1] += a0*wlo.y; acc[0][2] += a0*wlo.z; acc[0][3] += a0*wlo.w;
            acc[0][4] += a0*whi.x; acc[0][5] += a0*whi.y; acc[0][6] += a0*whi.z; acc[0][7] += a0*whi.w;
            acc[1][0] += a1*wlo.x; acc[1][1] += a1*wlo.y; acc[1][2] += a1*wlo.z; acc[1][3] += a1*wlo.w;
            acc[1][4] += a1*whi.x; acc[1][5] += a1*whi.y; acc[1][6] += a1*whi.z; acc[1][7] += a1*whi.w;
            acc[2][0] += a2*wlo.x; acc[2][1] += a2*wlo.y; acc[2][2] += a2*wlo.z; acc[2][3] += a2*wlo.w;
            acc[2][4] += a2*whi.x; acc[2][5] += a2*whi.y; acc[2][6] += a2*whi.z; acc[2][7] += a2*whi.w;
            acc[3][0] += a3*wlo.x; acc[3][1] += a3*wlo.y; acc[3][2] += a3*wlo.z; acc[3][3] += a3*wlo.w;
            acc[3][4] += a3*whi.x; acc[3][5] += a3*whi.y; acc[3][6] += a3*whi.z; acc[3][7] += a3*whi.w;
        }
        __syncthreads();
    }
    if (EPI == 0) {
        #pragma unroll
        for (int i = 0; i < 4; ++i) {
            int l = m0 + tm * 4 + i;
            if (NP == NR) {
                *(float4*)&outp[l * NR + n0 + tn * 4] =
                    make_float4(acc[i][0], acc[i][1], acc[i][2], acc[i][3]);
                *(float4*)&outp[l * NR + n0 + 32 + tn * 4] =
                    make_float4(acc[i][4], acc[i][5], acc[i][6], acc[i][7]);
            } else {
                #pragma unroll
                for (int j = 0; j < 4; ++j) {
                    int n = n0 + tn * 4 + j;
                    if (n < NR) outp[l * NR + n] = acc[i][j];
                    int n2 = n0 + 32 + tn * 4 + j;
                    if (n2 < NR) outp[l * NR + n2] = acc[i][j + 4];
                }
            }
        }
    } else if (EPI == 1) {
        float mx = fmaxf(slg[0], fmaxf(slg[1], slg[2]));
        float e0 = expf(slg[0] - mx), e1 = expf(slg[1] - mx), e2 = expf(slg[2] - mx);
        int br = n0 >> 6;
        float wt = ((br == 0) ? e0 : (br == 1) ? e1 : e2) / (e0 + e1 + e2);
        int b = m0 >> 10;
        #pragma unroll
        for (int i = 0; i < 4; ++i) {
            int l = m0 + tm * 4 + i;
            float gx = g_offs[l * 3 + 0];
            float gy = g_offs[l * 3 + 1];
            float gz = g_offs[l * 3 + 2];
            float ixf = ((gx + 1.f) * (float)Ww - 1.f) * 0.5f;
            float iyf = ((gy + 1.f) * (float)Hh - 1.f) * 0.5f;
            float izf = ((gz + 1.f) * (float)Dd - 1.f) * 0.5f;
            float x0f = floorf(ixf), y0f = floorf(iyf), z0f = floorf(izf);
            int idxs[8]; float w8[8];
            int corner = 0;
            #pragma unroll
            for (int dz = 0; dz < 2; ++dz)
            #pragma unroll
            for (int dy = 0; dy < 2; ++dy)
            #pragma unroll
            for (int dx = 0; dx < 2; ++dx) {
                float xc = x0f + dx, yc = y0f + dy, zc = z0f + dz;
                float wg = (1.f - fabsf(ixf - xc)) * (1.f - fabsf(iyf - yc))
                         * (1.f - fabsf(izf - zc));
                bool valid = (xc >= 0.f) && (xc < (float)Ww) && (yc >= 0.f)
                          && (yc < (float)Hh) && (zc >= 0.f) && (zc < (float)Dd);
                int xi_ = (int)fminf(fmaxf(xc, 0.f), (float)(Ww - 1));
                int yi_ = (int)fminf(fmaxf(yc, 0.f), (float)(Hh - 1));
                int zi_ = (int)fminf(fmaxf(zc, 0.f), (float)(Dd - 1));
                idxs[corner] = b * LL + (zi_ * Hh + yi_) * Ww + xi_;
                w8[corner] = wg * (valid ? 1.f : 0.f);
                ++corner;
            }
            #pragma unroll
            for (int j = 0; j < 4; ++j) {
                int c1 = n0 + tn * 4 + j;
                int c2 = n0 + 32 + tn * 4 + j;
                float pe1 = 0.f, pe2 = 0.f;
                #pragma unroll
                for (int k = 0; k < 8; ++k) {
                    pe1 += g_xT[idxs[k] * Cc + c1] * w8[k];
                    pe2 += g_xT[idxs[k] * Cc + c2] * w8[k];
                }
                outp[l * Cc + c1] = (acc[i][j] + g_bcat[c1]) * wt + pe1;
                outp[l * Cc + c2] = (acc[i][j + 4] + g_bcat[c2]) * wt + pe2;
            }
        }
    } else {
        float* sT = &sW[0][0];
        #pragma unroll
        for (int i = 0; i < 4; ++i) {
            int ml = tm * 4 + i;
            #pragma unroll
            for (int j = 0; j < 4; ++j) {
                sT[(tn * 4 + j) * 68 + ml] = acc[i][j];
                sT[(32 + tn * 4 + j) * 68 + ml] = acc[i][j + 4];
            }
        }
        __syncthreads();
        int b = m0 >> 10, l0 = m0 & 1023;
        #pragma unroll
        for (int t = 0; t < 8; ++t) {
            int idx = tid + t * 128;
            int nr = idx >> 4, c4 = idx & 15;
            float4 v = *(const float4*)&sT[nr * 68 + c4 * 4];
            *(float4*)&outp[((b * Cc + n0 + nr) << 10) + l0 + c4 * 4] = v;
        }
        if (tid < 64) {
            float s = 0.f;
            #pragma unroll 8
            for (int ll = 0; ll < 64; ++ll) s += sT[tid * 68 + ll];
            int ltile = (m0 & 1023) >> 6;
            g_p2p[(b * 16 + ltile) * Cc + n0 + tid] = s;
        }
    }
}

// ---------------- depthwise causal conv + silu (float4 over d) ----------------
__global__ void dwconv_kernel(const float* __restrict__ cw, const float* __restrict__ cb) {
    int v = blockIdx.x * 256 + threadIdx.x;
    if (v >= MM * 96) return;
    int d4 = (v % 96) * 4;
    int bl = v / 96;
    int l = bl & 1023, b = bl >> 10;
    const float* base = g_xz + (b * LL) * (2 * DIN) + d4;
    float4 s = *(const float4*)&cb[d4];
    float4 w0 = *(const float4*)&cw[(d4 + 0) * DCONV];
    float4 w1 = *(const float4*)&cw[(d4 + 1) * DCONV];
    float4 w2 = *(const float4*)&cw[(d4 + 2) * DCONV];
    float4 w3 = *(const float4*)&cw[(d4 + 3) * DCONV];
    const float* wk0 = (const float*)&w0;
    const float* wk1 = (const float*)&w1;
    const float* wk2 = (const float*)&w2;
    const float* wk3 = (const float*)&w3;
    #pragma unroll
    for (int k = 0; k < DCONV; ++k) {
        int ll = l - (DCONV - 1) + k;
        if (ll >= 0) {
            float4 xv = *(const float4*)&base[ll * (2 * DIN)];
            s.x += xv.x * wk0[k];
            s.y += xv.y * wk1[k];
            s.z += xv.z * wk2[k];
            s.w += xv.w * wk3[k];
        }
    }
    float4 r;
    r.x = s.x * sigmoidf_(s.x);
    r.y = s.y * sigmoidf_(s.y);
    r.z = s.z * sigmoidf_(s.z);
    r.w = s.w * sigmoidf_(s.w);
    *(float4*)&g_xi[bl * DIN + d4] = r;
}

// ---------------- delta (float4 over d, shared row loads) ----------------
__global__ void delta_kernel(const float* __restrict__ dtw, const float* __restrict__ dtb) {
    __shared__ float sdt[DIN * DTRANK];
    int tid = threadIdx.x;
    for (int k = tid; k < DIN * DTRANK; k += 256) sdt[k] = dtw[k];
    __syncthreads();
    int v = blockIdx.x * 256 + tid;
    if (v >= MM * 96) return;
    int d4 = (v % 96) * 4;
    int bl = v / 96;
    const float* row = g_dbl + bl * 140;
    float rr[DTRANK];
    #pragma unroll
    for (int r = 0; r < DTRANK; ++r) rr[r] = __ldg(row + r);
    float4 s = *(const float4*)&dtb[d4];
    #pragma unroll
    for (int r = 0; r < DTRANK; ++r) {
        s.x += rr[r] * sdt[(d4 + 0) * DTRANK + r];
        s.y += rr[r] * sdt[(d4 + 1) * DTRANK + r];
        s.z += rr[r] * sdt[(d4 + 2) * DTRANK + r];
        s.w += rr[r] * sdt[(d4 + 3) * DTRANK + r];
    }
    float4 o;
    o.x = softplusf_(s.x); o.y = softplusf_(s.y);
    o.z = softplusf_(s.z); o.w = softplusf_(s.w);
    *(float4*)&g_delta[bl * DIN + d4] = o;
}

// ---------------- selective scan: 2 warps per (b,d), 1 state/lane ----------------
// grid 384 blocks x 256 threads = 3072 warps = 1536 pairs x 2 halves
__global__ void scan_kernel(const float* __restrict__ a_log, const float* __restrict__ Dskip) {
    __shared__ float sm[8][32][33];
    __shared__ float sP[4][32];
    int wIn = threadIdx.x >> 5, lane = threadIdx.x & 31;
    int pairIn = wIn >> 1, half = wIn & 1;
    int bd = blockIdx.x * 4 + pairIn;
    int b = bd / DIN, d = bd % DIN;
    float (*S)[33] = sm[wIn];
    float a = -expf(a_log[d * DSTATE + half * 32 + lane]);
    float dsk = Dskip[d];
    float h = 0.f;
    const float* dptr = g_delta + b * LL * DIN + d;
    const float* uptr = g_xi + b * LL * DIN + d;
    const float* dblb = g_dbl + b * LL * 140;
    const float* zbase = g_xz + b * LL * (2 * DIN) + DIN + d;
    float* yo = g_y + b * LL * DIN + d;
    int boff = 12 + half * 32 + lane;
    int coff = 76 + half * 32 + lane;
    for (int l0 = 0; l0 < LL; l0 += 32) {
        #pragma unroll 4
        for (int j = 0; j < 32; ++j) {
            int l = l0 + j;
            float dt = __ldg(dptr + l * DIN);
            float u = __ldg(uptr + l * DIN);
            const float* row = dblb + l * 140;
            float bv = __ldg(row + boff);
            float cv = __ldg(row + coff);
            h = __expf(dt * a) * h + dt * u * bv;
            S[j][lane] = h * cv;
        }
        __syncwarp();
        float s = 0.f;
        #pragma unroll
        for (int k = 0; k < 32; ++k) s += S[lane][k];
        if (half == 1) sP[pairIn][lane] = s;
        __syncthreads();
        if (half == 0) {
            int l = l0 + lane;
            float total = s + sP[pairIn][lane];
            float u2 = __ldg(uptr + l * DIN);
            float z = __ldg(zbase + l * (2 * DIN));
            yo[l * DIN] = (total + u2 * dsk) * (z * sigmoidf_(z));
        }
        __syncthreads();
    }
}

// ---------------- fused channel attention + scale (with partial-mean reduce) ----------------
__global__ void ca_scale_kernel(const float* __restrict__ w1, const float* __restrict__ b1,
                                const float* __restrict__ w2, const float* __restrict__ b2,
                                float* __restrict__ out) {
    int b = blockIdx.x >> 5;
    int chunk = blockIdx.x & 31;
    int tid = threadIdx.x;
    __shared__ float p[Cc];
    __shared__ float hid[48];
    __shared__ float attn[Cc];
    if (tid < Cc) {
        float s = 0.f;
        #pragma unroll
        for (int t = 0; t < 16; ++t) s += g_p2p[(b * 16 + t) * Cc + tid];
        p[tid] = s * (1.f / (float)LL);
    }
    __syncthreads();
    if (tid < 48) {
        const float* wr = w1 + tid * Cc;
        float s = b1[tid];
        #pragma unroll 8
        for (int k = 0; k < Cc; ++k) s += p[k] * wr[k];
        hid[tid] = geluf_(s);
    }
    __syncthreads();
    if (tid < Cc) {
        const float* wr2 = w2 + tid * 48;
        float s = b2[tid];
        #pragma unroll
        for (int j = 0; j < 48; ++j) s += hid[j] * wr2[j];
        attn[tid] = sigmoidf_(s);
    }
    __syncthreads();
    int l0 = chunk * 32;
    for (int e = tid; e < Cc * 32; e += 256) {
        int c = e >> 5, l = l0 + (e & 31);
        out[(b * Cc + c) * LL + l] *= attn[c];
    }
}

extern "C" void kernel_launch(void* const* d_in, const int* in_sizes, int n_in,
                              void* d_out, int out_size) {
    const float* x         = (const float*)d_in[0];
    const float* px_w      = (const float*)d_in[1];
    const float* px_b      = (const float*)d_in[2];
    const float* py_w      = (const float*)d_in[3];
    const float* py_b      = (const float*)d_in[4];
    const float* pz_w      = (const float*)d_in[5];
    const float* pz_b      = (const float*)d_in[6];
    const float* wg_w      = (const float*)d_in[7];
    const float* wg_b      = (const float*)d_in[8];
    const float* off_w1    = (const float*)d_in[9];
    const float* off_b1    = (const float*)d_in[10];
    const float* off_w2    = (const float*)d_in[11];
    const float* off_b2    = (const float*)d_in[12];
    const float* in_proj_w = (const float*)d_in[13];
    const float* conv_w    = (const float*)d_in[14];
    const float* conv_b    = (const float*)d_in[15];
    const float* x_proj_w  = (const float*)d_in[16];
    const float* dt_proj_w = (const float*)d_in[17];
    const float* dt_proj_b = (const float*)d_in[18];
    const float* A_log     = (const float*)d_in[19];
    const float* D_skip    = (const float*)d_in[20];
    const float* out_proj_w = (const float*)d_in[21];
    const float* ca_w1     = (const float*)d_in[22];
    const float* ca_b1     = (const float*)d_in[23];
    const float* ca_w2     = (const float*)d_in[24];
    const float* ca_b2     = (const float*)d_in[25];
    float* out = (float*)d_out;

    float *g_xT_p, *g_xs_p, *g_xz_p, *g_xi_p, *g_dbl_p, *g_y_p;
    float *g_tin_p, *g_tcat_p, *g_tx_p, *g_tout_p;
    cudaGetSymbolAddress((void**)&g_xT_p, g_xT);
    cudaGetSymbolAddress((void**)&g_xs_p, g_xs);
    cudaGetSymbolAddress((void**)&g_xz_p, g_xz);
    cudaGetSymbolAddress((void**)&g_xi_p, g_xi);
    cudaGetSymbolAddress((void**)&g_dbl_p, g_dbl);
    cudaGetSymbolAddress((void**)&g_y_p, g_y);
    cudaGetSymbolAddress((void**)&g_tin_p, g_tin);
    cudaGetSymbolAddress((void**)&g_tcat_p, g_tcat);
    cudaGetSymbolAddress((void**)&g_tx_p, g_tx);
    cudaGetSymbolAddress((void**)&g_tout_p, g_tout);

    prepxt_kernel<<<1536 + PREP_BLKS, 256>>>(x, in_proj_w, px_w, py_w, pz_w,
                                             px_b, py_b, pz_b, x_proj_w, out_proj_w, off_w1);
    conv1_kernel<<<dim3(64, 27), 128>>>();
    hidred_kernel<<<(HIDN / 4 + 255) / 256, 256>>>(off_b1);
    conv2_kernel<<<MM / 4, 128>>>(off_w2, off_b2);
    gemm64<Cc, Cc, Cc, 1><<<dim3(64, 3), 128>>>(g_xT_p, g_tcat_p, g_xs_p, wg_w, wg_b);
    gemm64<Cc, 768, 768, 0><<<dim3(64, 12), 128>>>(g_xs_p, g_tin_p, g_xz_p, nullptr, nullptr);
    dwconv_kernel<<<(MM * 96 + 255) / 256, 256>>>(conv_w, conv_b);
    gemm64<DIN, 192, 140, 0><<<dim3(64, 3), 128>>>(g_xi_p, g_tx_p, g_dbl_p, nullptr, nullptr);
    delta_kernel<<<(MM * 96 + 255) / 256, 256>>>(dt_proj_w, dt_proj_b);
    scan_kernel<<<384, 256>>>(A_log, D_skip);
    gemm64<DIN, 192, 192, 2><<<dim3(64, 3), 128>>>(g_y_p, g_tout_p, out, nullptr, nullptr);
    ca_scale_kernel<<<Bn * 32, 256>>>(ca_w1, ca_b1, ca_w2, ca_b2, out);
}